// round 16
// baseline (speedup 1.0000x reference)
#include <cuda_runtime.h>
#include <cuda_fp16.h>

#define N       4096
#define NB      128     // persistent blocks, 1/SM, co-resident wave 1
#define NT      1024
#define RPB     32      // rows per block
#define NIT8    24      // fp8 (e4m3) iterations (validated floor-reach)
#define NIT16   2       // fp16 refinement iterations (26 total; validated 9.4e-5)
#define PREF_ROWS 16    // A-strip rows resident in SMEM

// dynamic SMEM layout
#define SM_STRIP   (RPB * N)                 // 131072 B : K^T strip, e4m3 (setup: 4 transpose tiles)
#define SM_PREF    (PREF_ROWS * N)           // 65536 B  : first half of A-strip, e4m3
#define SM_VEC     (N * 4)                   // 16384 B  : fp32 vector
#define SM_VH      (N * 2)                   // 8192 B   : fp16 vector
#define SM_PART    (RPB * 4 * 4)             // 512 B
#define SM_AF      (RPB * 4)                 // 128 B
#define SMEM_DYN   (SM_STRIP + SM_PREF + SM_VEC + SM_VH + SM_PART + SM_AF)   // 221,824 B

// ---- persistent device scratch ----
__device__ __align__(16) __half        g_Kh [(size_t)N * N];   // K fp16 row-major (32 MB)
__device__ __align__(16) __half        g_KhT[(size_t)N * N];   // K^T fp16         (32 MB)
__device__ __align__(16) unsigned char g_K8 [(size_t)N * N];   // K e4m3           (16 MB)
__device__ __align__(16) float  g_AFf[N];
__device__ __align__(16) __half g_AFh[N];
__device__ __align__(16) float  g_BFf[N];
__device__ __align__(16) __half g_BFh[N];
__device__ unsigned int g_bar;

__global__ void reset_bar_kernel() { g_bar = 0u; }

// ---- full grid barrier (setup/gather) ----
__device__ __forceinline__ void grid_sync(unsigned target) {
    __syncthreads();
    if (threadIdx.x == 0) {
        asm volatile("red.release.gpu.global.add.u32 [%0], %1;"
                     :: "l"(&g_bar), "r"(1u) : "memory");
        unsigned v;
        do {
            asm volatile("ld.global.cg.u32 %0, [%1];" : "=r"(v) : "l"(&g_bar) : "memory");
        } while (v < target);
    }
    __syncthreads();
}

// ---- fast iteration barrier (R14/R15-proven) ----
__device__ __forceinline__ void grid_sync_pub(unsigned target) {
    if (threadIdx.x == 0) {
        asm volatile("red.release.gpu.global.add.u32 [%0], %1;"
                     :: "l"(&g_bar), "r"(1u) : "memory");
        unsigned v;
        do {
            asm volatile("ld.global.cg.u32 %0, [%1];" : "=r"(v) : "l"(&g_bar) : "memory");
        } while (v < target);
    }
    __syncthreads();
}

// ---- fp8 helpers ----
__device__ __forceinline__ unsigned h2_to_e4m3x2(unsigned h2bits) {
    unsigned short r;
    asm("cvt.rn.satfinite.e4m3x2.f16x2 %0, %1;" : "=h"(r) : "r"(h2bits));
    return (unsigned)r;
}
__device__ __forceinline__ __half2 e4m3x2_to_h2(unsigned short u) {
    unsigned r;
    asm("cvt.rn.f16x2.e4m3x2 %0, %1;" : "=r"(r) : "h"(u));
    return *reinterpret_cast<__half2*>(&r);
}

// publish 32-element segment fp32+fp16 (fp8 phases; warp 0 only)
__device__ __forceinline__ void publish_seg(float val, int i0, int lane,
                                            float* __restrict__ gf, __half* __restrict__ gh) {
    __stcg(gf + i0 + lane, val);
    const float vlo = __shfl_sync(0xffffffffu, val, (lane & 15) * 2);
    const float vhi = __shfl_sync(0xffffffffu, val, (lane & 15) * 2 + 1);
    if (lane < 16) {
        const __half2 h = __floats2half2_rn(vlo, vhi);
        __stcg((__half2*)(gh + i0) + lane, h);
    }
    __syncwarp();
}

// publish fp32 only (fp16 phases)
__device__ __forceinline__ void publish_seg_f(float val, int i0, int lane,
                                              float* __restrict__ gf) {
    __stcg(gf + i0 + lane, val);
    __syncwarp();
}

// inner fp8 accumulate: one 16-byte chunk (16 elems) vs two uint4 vector halves
__device__ __forceinline__ float fp8_chunk_dot(uint4 kd, const __half2* vha,
                                               const __half2* vhb) {
    __half2 a2 = __floats2half2_rn(0.f, 0.f);
    a2 = __hfma2(e4m3x2_to_h2((unsigned short)kd.x),         vha[0], a2);
    a2 = __hfma2(e4m3x2_to_h2((unsigned short)(kd.x >> 16)), vha[1], a2);
    a2 = __hfma2(e4m3x2_to_h2((unsigned short)kd.y),         vha[2], a2);
    a2 = __hfma2(e4m3x2_to_h2((unsigned short)(kd.y >> 16)), vha[3], a2);
    a2 = __hfma2(e4m3x2_to_h2((unsigned short)kd.z),         vhb[0], a2);
    a2 = __hfma2(e4m3x2_to_h2((unsigned short)(kd.z >> 16)), vhb[1], a2);
    a2 = __hfma2(e4m3x2_to_h2((unsigned short)kd.w),         vhb[2], a2);
    a2 = __hfma2(e4m3x2_to_h2((unsigned short)(kd.w >> 16)), vhb[3], a2);
    float2 f = __half22float2(a2);
    return f.x + f.y;
}

// B-phase fp8 dot: 4 rows x 1024 cols, all SMEM
__device__ __forceinline__ void dot8_smem(const unsigned char* __restrict__ Mp,
                                          const uint4* __restrict__ vh4, int lane,
                                          float acc[4])
{
#pragma unroll
    for (int s = 0; s < 2; ++s) {
        const int e0 = (s << 9) + (lane << 4);
        uint4 va = vh4[(e0 >> 3)];
        uint4 vb = vh4[(e0 >> 3) + 1];
        const __half2* vha = (const __half2*)&va;
        const __half2* vhb = (const __half2*)&vb;
#pragma unroll
        for (int r = 0; r < 4; ++r)
            acc[r] += fp8_chunk_dot(*(const uint4*)(Mp + (size_t)r * N + e0), vha, vhb);
    }
}

// A-phase fp8 dot, balanced: 2 rows from SMEM + 2 rows from L2 per warp group.
// acc = {smem row0, smem row1, gmem row0, gmem row1}
__device__ __forceinline__ void dot8_mixed(const unsigned char* __restrict__ Ms,
                                           const unsigned char* __restrict__ Mg,
                                           const uint4* __restrict__ vh4, int lane,
                                           float acc[4])
{
#pragma unroll
    for (int s = 0; s < 2; ++s) {
        const int e0 = (s << 9) + (lane << 4);
        // issue L2 loads first so their latency overlaps the SMEM work
        uint4 g0 = __ldcg((const uint4*)(Mg + e0));
        uint4 g1 = __ldcg((const uint4*)(Mg + (size_t)N + e0));
        uint4 va = vh4[(e0 >> 3)];
        uint4 vb = vh4[(e0 >> 3) + 1];
        const __half2* vha = (const __half2*)&va;
        const __half2* vhb = (const __half2*)&vb;
        acc[0] += fp8_chunk_dot(*(const uint4*)(Ms + e0),             vha, vhb);
        acc[1] += fp8_chunk_dot(*(const uint4*)(Ms + (size_t)N + e0), vha, vhb);
        acc[2] += fp8_chunk_dot(g0, vha, vhb);
        acc[3] += fp8_chunk_dot(g1, vha, vhb);
    }
}

__device__ __forceinline__ void warp_reduce_row(float a, int row, int q, int lane,
                                                float* __restrict__ s_part)
{
#pragma unroll
    for (int off = 16; off; off >>= 1) a += __shfl_xor_sync(0xffffffffu, a, off);
    if (lane == 0) s_part[(row << 2) + q] = a;
}

__device__ __forceinline__ void warp_reduce_part(float acc[4], int r0, int q, int lane,
                                                 float* __restrict__ s_part)
{
#pragma unroll
    for (int r = 0; r < 4; ++r) warp_reduce_row(acc[r], r0 + r, q, lane, s_part);
}

// fp16 strip dot (fp32 vector from SMEM + fp32 accum), rows from L2
__device__ __forceinline__ void dot16(const __half* __restrict__ M,
                                      const float*  __restrict__ s_vec,
                                      int i0, int g, int q, int lane,
                                      float* __restrict__ s_part)
{
    const int c0 = q << 10;
    const int r0 = g << 2;
    const __half* Mp = M + (size_t)(i0 + r0) * N + c0;
    const float4* sv4 = (const float4*)(s_vec + c0);

    float acc[4] = {0.f, 0.f, 0.f, 0.f};
#pragma unroll
    for (int s = 0; s < 4; ++s) {
        const int i = (s << 8) + (lane << 3);
        const float4 v0 = sv4[(i >> 2)];
        const float4 v1 = sv4[(i >> 2) + 1];
#pragma unroll
        for (int r = 0; r < 4; ++r) {
            const float4 kr = __ldcg((const float4*)(Mp + (size_t)r * N + i));
            const __half2* h = (const __half2*)&kr;
            const float2 f0 = __half22float2(h[0]);
            const float2 f1 = __half22float2(h[1]);
            const float2 f2 = __half22float2(h[2]);
            const float2 f3 = __half22float2(h[3]);
            acc[r] += f0.x * v0.x + f0.y * v0.y + f1.x * v0.z + f1.y * v0.w
                    + f2.x * v1.x + f2.y * v1.y + f3.x * v1.z + f3.y * v1.w;
        }
    }
    warp_reduce_part(acc, r0, q, lane, s_part);
}

__global__ void __launch_bounds__(NT, 1)
competitive_kernel(const float* __restrict__ AT, const float* __restrict__ k,
                   const float* __restrict__ bt, float* __restrict__ C)
{
    extern __shared__ char s_dyn[];
    unsigned char* s_strip = (unsigned char*)s_dyn;                        // 128 KB K^T strip
    unsigned char* s_pref  = (unsigned char*)(s_dyn + SM_STRIP);           // 64 KB A-strip half
    float*   s_vec  = (float*)  (s_dyn + SM_STRIP + SM_PREF);              // 16 KB
    __half2* s_vh   = (__half2*)(s_dyn + SM_STRIP + SM_PREF + SM_VEC);     // 8 KB
    float*   s_part = (float*)  (s_dyn + SM_STRIP + SM_PREF + SM_VEC + SM_VH);
    float*   s_af   = (float*)  (s_dyn + SM_STRIP + SM_PREF + SM_VEC + SM_VH + SM_PART);

    const int tid  = threadIdx.x;
    const int w    = tid >> 5;
    const int lane = tid & 31;
    const int g    = w >> 2;                 // row group 0..7
    const int q    = w & 3;                  // column quarter 0..3
    const int bid  = blockIdx.x;
    const int i0   = bid * RPB;
    const int r0   = g << 2;
    const int c0   = q << 10;

    float r_at = 0.f, r_bt2 = 0.f;
    if (tid < RPB) {
        r_at = AT[i0 + tid];
        float b = bt[i0 + tid];
        r_bt2 = b * b;
    }

    // ---------- setup (fused, 4 tiles per sync round): Kh, K8, KhT ----------
    for (int t = 0; t < N / 64 / 4; ++t) {          // 16 rounds, 2 syncs each
#pragma unroll
        for (int tt = 0; tt < 4; ++tt) {
            const int j0 = (t * 4 + tt) * 64;
            float (*tl)[33] = (float(*)[33])(s_dyn + tt * 8448);
            const size_t roff = (size_t)(i0 + w) * N + j0;
            float2 v = __ldcs((const float2*)(k + roff) + lane);
            v.x *= v.x; v.y *= v.y;
            const __half2 h2 = __floats2half2_rn(v.x, v.y);
            *(__half2*)(g_Kh + roff + lane * 2) = h2;
            *(unsigned short*)(g_K8 + roff + lane * 2) =
                (unsigned short)h2_to_e4m3x2(*(const unsigned*)&h2);
            tl[lane * 2    ][w] = v.x;
            tl[lane * 2 + 1][w] = v.y;
        }
        __syncthreads();
#pragma unroll
        for (int tt = 0; tt < 4; ++tt) {
            const int j0 = (t * 4 + tt) * 64;
            float (*tl)[33] = (float(*)[33])(s_dyn + tt * 8448);
#pragma unroll
            for (int qq = 0; qq < 2; ++qq) {
                const int c = w * 2 + qq;
                g_KhT[(size_t)(j0 + c) * N + i0 + lane] = __float2half(tl[c][lane]);
            }
        }
        __syncthreads();
    }
    if (tid < 32) publish_seg(r_at, i0, lane, g_AFf, g_AFh);    // initial AF (f32 + f16)

    unsigned tgt = 0;
    grid_sync(tgt += NB);     // full barrier: all warps wrote Kh/KhT/K8

    // ---------- gather K^T strip (fp8) + half of A-strip into SMEM ----------
    {
        const uint4* src = (const uint4*)(g_KhT + (size_t)i0 * N);
        uint2* dst = (uint2*)s_strip;
#pragma unroll 4
        for (int s = 0; s < 16; ++s) {
            const int idx = s * NT + tid;
            uint4 h8 = __ldcg(src + idx);
            uint2 o;
            o.x = h2_to_e4m3x2(h8.x) | (h2_to_e4m3x2(h8.y) << 16);
            o.y = h2_to_e4m3x2(h8.z) | (h2_to_e4m3x2(h8.w) << 16);
            dst[idx] = o;
        }
        const uint4* asrc = (const uint4*)(g_K8 + (size_t)i0 * N);
        uint4* adst = (uint4*)s_pref;
#pragma unroll
        for (int s = 0; s < 4; ++s) {
            const int idx = s * NT + tid;
            adst[idx] = __ldcg(asrc + idx);
        }
    }
    __syncthreads();

    // ---------- fp8 iterations ----------
    for (int it = 0; it < NIT8; ++it) {
        // BF = bt^2 / (1 + K^T @ AF)  -- strip fully SMEM
        ((uint2*)s_vh)[tid] = __ldcg((const uint2*)g_AFh + tid);
        __syncthreads();
        {
            float acc[4] = {0.f, 0.f, 0.f, 0.f};
            const uint4* vh4 = (const uint4*)((const char*)s_vh + (q << 11));
            dot8_smem(s_strip + (size_t)r0 * N + c0, vh4, lane, acc);
            warp_reduce_part(acc, r0, q, lane, s_part);
        }
        __syncthreads();
        if (tid < 32) {
            const float a = s_part[tid * 4] + s_part[tid * 4 + 1]
                          + s_part[tid * 4 + 2] + s_part[tid * 4 + 3];
            publish_seg(r_bt2 / (1.0f + a), i0, lane, g_BFf, g_BFh);
        }
        grid_sync_pub(tgt += NB);

        // AF = AT / (1 + K @ BF)  -- balanced: every group does 2 SMEM + 2 L2 rows
        ((uint2*)s_vh)[tid] = __ldcg((const uint2*)g_BFh + tid);
        __syncthreads();
        {
            float acc[4] = {0.f, 0.f, 0.f, 0.f};
            const uint4* vh4 = (const uint4*)((const char*)s_vh + (q << 11));
            const int rs = g << 1;                            // SMEM rows 2g, 2g+1
            const int rg = PREF_ROWS + (g << 1);              // L2 rows 16+2g, 16+2g+1
            dot8_mixed(s_pref + (size_t)rs * N + c0,
                       g_K8 + (size_t)(i0 + rg) * N + c0,
                       vh4, lane, acc);
            warp_reduce_row(acc[0], rs,     q, lane, s_part);
            warp_reduce_row(acc[1], rs + 1, q, lane, s_part);
            warp_reduce_row(acc[2], rg,     q, lane, s_part);
            warp_reduce_row(acc[3], rg + 1, q, lane, s_part);
        }
        __syncthreads();
        if (tid < 32) {
            const float a = s_part[tid * 4] + s_part[tid * 4 + 1]
                          + s_part[tid * 4 + 2] + s_part[tid * 4 + 3];
            publish_seg(r_at / (1.0f + a), i0, lane, g_AFf, g_AFh);
        }
        grid_sync_pub(tgt += NB);
    }

    // ---------- fp16 refinement iterations (fp32-only publishes) ----------
    for (int it = 0; it < NIT16; ++it) {
        ((float4*)s_vec)[tid] = __ldcg((const float4*)g_AFf + tid);
        __syncthreads();
        dot16(g_KhT, s_vec, i0, g, q, lane, s_part);
        __syncthreads();
        if (tid < 32) {
            const float a = s_part[tid * 4] + s_part[tid * 4 + 1]
                          + s_part[tid * 4 + 2] + s_part[tid * 4 + 3];
            publish_seg_f(r_bt2 / (1.0f + a), i0, lane, g_BFf);
        }
        grid_sync_pub(tgt += NB);

        ((float4*)s_vec)[tid] = __ldcg((const float4*)g_BFf + tid);
        __syncthreads();
        dot16(g_Kh, s_vec, i0, g, q, lane, s_part);
        __syncthreads();
        if (tid < 32) {
            const float a = s_part[tid * 4] + s_part[tid * 4 + 1]
                          + s_part[tid * 4 + 2] + s_part[tid * 4 + 3];
            const float af = r_at / (1.0f + a);
            if (it == NIT16 - 1) s_af[tid] = af;           // final: keep local
            else                 publish_seg_f(af, i0, lane, g_AFf);
        }
        if (it != NIT16 - 1) grid_sync_pub(tgt += NB);
        else                 __syncthreads();              // BF already grid-synced
    }

    // ---------- output: C[i][j] = AF_i * k_ij^2 * BF_j  (fp32 k, streaming stores) ----------
    ((float4*)s_vec)[tid] = __ldcg((const float4*)g_BFf + tid);
    __syncthreads();

    const float af = s_af[w];                              // warp w -> row i0 + w
    const float4* sv4 = (const float4*)s_vec;
#pragma unroll 8
    for (int s = 0; s < 32; ++s) {
        const int j = s * 128 + lane * 4;
        const size_t off = (size_t)(i0 + w) * N + j;
        const float4 kv = __ldcs((const float4*)(k + off));
        const float4 bv = sv4[j >> 2];
        float4 c4;
        c4.x = af * kv.x * kv.x * bv.x;
        c4.y = af * kv.y * kv.y * bv.y;
        c4.z = af * kv.z * kv.z * bv.z;
        c4.w = af * kv.w * kv.w * bv.w;
        __stcs((float4*)(C + off), c4);
    }
}

extern "C" void kernel_launch(void* const* d_in, const int* in_sizes, int n_in,
                              void* d_out, int out_size) {
    const float* AT = (const float*)d_in[0];
    const float* k  = (const float*)d_in[1];
    const float* bt = (const float*)d_in[2];
    float* C = (float*)d_out;

    cudaFuncSetAttribute(competitive_kernel,
                         cudaFuncAttributeMaxDynamicSharedMemorySize, SMEM_DYN);
    reset_bar_kernel<<<1, 1>>>();
    competitive_kernel<<<NB, NT, SMEM_DYN>>>(AT, k, bt, C);
}

// round 17
// speedup vs baseline: 1.0395x; 1.0395x over previous
#include <cuda_runtime.h>
#include <cuda_fp16.h>

#define N       4096
#define NB      128     // persistent blocks, 1/SM, co-resident wave 1
#define NT      1024
#define RPB     32      // rows per block
#define NIT8    24      // fp8 (e4m3) iterations (validated floor-reach)
#define NIT16   2       // fp16 refinement iterations (26 total; validated 9.4e-5)
#define PREF_ROWS 16    // A-strip rows resident in SMEM

// dynamic SMEM layout
#define SM_STRIP   (RPB * N)                 // 131072 B : K^T strip, e4m3 (setup: 4 transpose tiles)
#define SM_PREF    (PREF_ROWS * N)           // 65536 B  : first half of A-strip, e4m3
#define SM_VEC     (N * 4)                   // 16384 B  : fp32 vector
#define SM_VH      (N * 2)                   // 8192 B   : fp16 vector
#define SM_PART    (RPB * 4 * 4)             // 512 B
#define SM_AF      (RPB * 4)                 // 128 B
#define SMEM_DYN   (SM_STRIP + SM_PREF + SM_VEC + SM_VH + SM_PART + SM_AF)   // 221,824 B

// ---- persistent device scratch ----
__device__ __align__(16) __half        g_Kh [(size_t)N * N];   // K fp16 row-major (32 MB)
__device__ __align__(16) __half        g_KhT[(size_t)N * N];   // K^T fp16         (32 MB)
__device__ __align__(16) unsigned char g_K8 [(size_t)N * N];   // K e4m3           (16 MB)
__device__ __align__(16) float  g_AFf[N];
__device__ __align__(16) __half g_AFh[N];
__device__ __align__(16) float  g_BFf[N];
__device__ __align__(16) __half g_BFh[N];
__device__ unsigned int g_bar;

__global__ void reset_bar_kernel() { g_bar = 0u; }

// ---- full grid barrier (setup/gather) ----
__device__ __forceinline__ void grid_sync(unsigned target) {
    __syncthreads();
    if (threadIdx.x == 0) {
        asm volatile("red.release.gpu.global.add.u32 [%0], %1;"
                     :: "l"(&g_bar), "r"(1u) : "memory");
        unsigned v;
        do {
            asm volatile("ld.global.cg.u32 %0, [%1];" : "=r"(v) : "l"(&g_bar) : "memory");
        } while (v < target);
    }
    __syncthreads();
}

// ---- fast iteration barrier (R14/R15-proven): publisher warp's stores are
//      ordered via __syncwarp before thread 0's cumulative release; other
//      warps park at the closing BAR (no arbiter starvation). ----
__device__ __forceinline__ void grid_sync_pub(unsigned target) {
    if (threadIdx.x == 0) {
        asm volatile("red.release.gpu.global.add.u32 [%0], %1;"
                     :: "l"(&g_bar), "r"(1u) : "memory");
        unsigned v;
        do {
            asm volatile("ld.global.cg.u32 %0, [%1];" : "=r"(v) : "l"(&g_bar) : "memory");
        } while (v < target);
    }
    __syncthreads();
}

// ---- fp8 helpers ----
__device__ __forceinline__ unsigned h2_to_e4m3x2(unsigned h2bits) {
    unsigned short r;
    asm("cvt.rn.satfinite.e4m3x2.f16x2 %0, %1;" : "=h"(r) : "r"(h2bits));
    return (unsigned)r;
}
__device__ __forceinline__ __half2 e4m3x2_to_h2(unsigned short u) {
    unsigned r;
    asm("cvt.rn.f16x2.e4m3x2 %0, %1;" : "=r"(r) : "h"(u));
    return *reinterpret_cast<__half2*>(&r);
}

// publish 32-element segment fp32+fp16 (fp8 phases; warp 0 only)
__device__ __forceinline__ void publish_seg(float val, int i0, int lane,
                                            float* __restrict__ gf, __half* __restrict__ gh) {
    __stcg(gf + i0 + lane, val);
    const float vlo = __shfl_sync(0xffffffffu, val, (lane & 15) * 2);
    const float vhi = __shfl_sync(0xffffffffu, val, (lane & 15) * 2 + 1);
    if (lane < 16) {
        const __half2 h = __floats2half2_rn(vlo, vhi);
        __stcg((__half2*)(gh + i0) + lane, h);
    }
    __syncwarp();
}

// publish fp32 only (fp16 phases; fp16 mirror is dead there)
__device__ __forceinline__ void publish_seg_f(float val, int i0, int lane,
                                              float* __restrict__ gf) {
    __stcg(gf + i0 + lane, val);
    __syncwarp();
}

// fp8 dot: 4 rows x 1024 cols; matrix from SMEM or L2; fp16 vector quarter from SMEM
__device__ __forceinline__ void dot8_body(const unsigned char* __restrict__ Mp, bool glob,
                                          const uint4* __restrict__ vh4, int lane,
                                          float acc[4])
{
#pragma unroll
    for (int s = 0; s < 2; ++s) {
        const int e0 = (s << 9) + (lane << 4);               // 16 fp8 elems per lane per step
        uint4 va = vh4[(e0 >> 3)];
        uint4 vb = vh4[(e0 >> 3) + 1];
        const __half2* vha = (const __half2*)&va;
        const __half2* vhb = (const __half2*)&vb;
#pragma unroll
        for (int r = 0; r < 4; ++r) {
            const uint4* p = (const uint4*)(Mp + (size_t)r * N + e0);
            uint4 kd = glob ? __ldcg(p) : *p;                // LDS when SMEM provenance
            __half2 a2 = __floats2half2_rn(0.f, 0.f);
            a2 = __hfma2(e4m3x2_to_h2((unsigned short)kd.x),         vha[0], a2);
            a2 = __hfma2(e4m3x2_to_h2((unsigned short)(kd.x >> 16)), vha[1], a2);
            a2 = __hfma2(e4m3x2_to_h2((unsigned short)kd.y),         vha[2], a2);
            a2 = __hfma2(e4m3x2_to_h2((unsigned short)(kd.y >> 16)), vha[3], a2);
            a2 = __hfma2(e4m3x2_to_h2((unsigned short)kd.z),         vhb[0], a2);
            a2 = __hfma2(e4m3x2_to_h2((unsigned short)(kd.z >> 16)), vhb[1], a2);
            a2 = __hfma2(e4m3x2_to_h2((unsigned short)kd.w),         vhb[2], a2);
            a2 = __hfma2(e4m3x2_to_h2((unsigned short)(kd.w >> 16)), vhb[3], a2);
            float2 f = __half22float2(a2);
            acc[r] += f.x + f.y;
        }
    }
}

__device__ __forceinline__ void warp_reduce_part(float acc[4], int r0, int q, int lane,
                                                 float* __restrict__ s_part)
{
#pragma unroll
    for (int r = 0; r < 4; ++r) {
        float a = acc[r];
#pragma unroll
        for (int off = 16; off; off >>= 1) a += __shfl_xor_sync(0xffffffffu, a, off);
        if (lane == 0) s_part[((r0 + r) << 2) + q] = a;
    }
}

// fp16 strip dot (fp32 vector from SMEM + fp32 accum), rows from L2
__device__ __forceinline__ void dot16(const __half* __restrict__ M,
                                      const float*  __restrict__ s_vec,
                                      int i0, int g, int q, int lane,
                                      float* __restrict__ s_part)
{
    const int c0 = q << 10;
    const int r0 = g << 2;
    const __half* Mp = M + (size_t)(i0 + r0) * N + c0;
    const float4* sv4 = (const float4*)(s_vec + c0);

    float acc[4] = {0.f, 0.f, 0.f, 0.f};
#pragma unroll
    for (int s = 0; s < 4; ++s) {
        const int i = (s << 8) + (lane << 3);
        const float4 v0 = sv4[(i >> 2)];
        const float4 v1 = sv4[(i >> 2) + 1];
#pragma unroll
        for (int r = 0; r < 4; ++r) {
            const float4 kr = __ldcg((const float4*)(Mp + (size_t)r * N + i));
            const __half2* h = (const __half2*)&kr;
            const float2 f0 = __half22float2(h[0]);
            const float2 f1 = __half22float2(h[1]);
            const float2 f2 = __half22float2(h[2]);
            const float2 f3 = __half22float2(h[3]);
            acc[r] += f0.x * v0.x + f0.y * v0.y + f1.x * v0.z + f1.y * v0.w
                    + f2.x * v1.x + f2.y * v1.y + f3.x * v1.z + f3.y * v1.w;
        }
    }
    warp_reduce_part(acc, r0, q, lane, s_part);
}

__global__ void __launch_bounds__(NT, 1)
competitive_kernel(const float* __restrict__ AT, const float* __restrict__ k,
                   const float* __restrict__ bt, float* __restrict__ C)
{
    extern __shared__ char s_dyn[];
    unsigned char* s_strip = (unsigned char*)s_dyn;                        // 128 KB K^T strip
    unsigned char* s_pref  = (unsigned char*)(s_dyn + SM_STRIP);           // 64 KB A-strip half
    float*   s_vec  = (float*)  (s_dyn + SM_STRIP + SM_PREF);              // 16 KB
    __half2* s_vh   = (__half2*)(s_dyn + SM_STRIP + SM_PREF + SM_VEC);     // 8 KB
    float*   s_part = (float*)  (s_dyn + SM_STRIP + SM_PREF + SM_VEC + SM_VH);
    float*   s_af   = (float*)  (s_dyn + SM_STRIP + SM_PREF + SM_VEC + SM_VH + SM_PART);

    const int tid  = threadIdx.x;
    const int w    = tid >> 5;
    const int lane = tid & 31;
    const int g    = w >> 2;                 // row group 0..7
    const int q    = w & 3;                  // column quarter 0..3
    const int bid  = blockIdx.x;
    const int i0   = bid * RPB;
    const int r0   = g << 2;
    const int c0   = q << 10;

    float r_at = 0.f, r_bt2 = 0.f;
    if (tid < RPB) {
        r_at = AT[i0 + tid];
        float b = bt[i0 + tid];
        r_bt2 = b * b;
    }

    // ---------- setup (fused, 4 tiles per sync round): Kh, K8, KhT ----------
    for (int t = 0; t < N / 64 / 4; ++t) {          // 16 rounds, 2 syncs each
#pragma unroll
        for (int tt = 0; tt < 4; ++tt) {
            const int j0 = (t * 4 + tt) * 64;
            float (*tl)[33] = (float(*)[33])(s_dyn + tt * 8448);
            const size_t roff = (size_t)(i0 + w) * N + j0;
            float2 v = __ldcs((const float2*)(k + roff) + lane);
            v.x *= v.x; v.y *= v.y;
            const __half2 h2 = __floats2half2_rn(v.x, v.y);
            *(__half2*)(g_Kh + roff + lane * 2) = h2;
            *(unsigned short*)(g_K8 + roff + lane * 2) =
                (unsigned short)h2_to_e4m3x2(*(const unsigned*)&h2);
            tl[lane * 2    ][w] = v.x;
            tl[lane * 2 + 1][w] = v.y;
        }
        __syncthreads();
#pragma unroll
        for (int tt = 0; tt < 4; ++tt) {
            const int j0 = (t * 4 + tt) * 64;
            float (*tl)[33] = (float(*)[33])(s_dyn + tt * 8448);
#pragma unroll
            for (int qq = 0; qq < 2; ++qq) {
                const int c = w * 2 + qq;
                g_KhT[(size_t)(j0 + c) * N + i0 + lane] = __float2half(tl[c][lane]);
            }
        }
        __syncthreads();
    }
    if (tid < 32) publish_seg(r_at, i0, lane, g_AFf, g_AFh);    // initial AF (f32 + f16)

    unsigned tgt = 0;
    grid_sync(tgt += NB);     // full barrier: all warps wrote Kh/KhT/K8

    // ---------- gather K^T strip (fp8) + half of A-strip into SMEM ----------
    {
        const uint4* src = (const uint4*)(g_KhT + (size_t)i0 * N);
        uint2* dst = (uint2*)s_strip;
#pragma unroll 4
        for (int s = 0; s < 16; ++s) {
            const int idx = s * NT + tid;
            uint4 h8 = __ldcg(src + idx);
            uint2 o;
            o.x = h2_to_e4m3x2(h8.x) | (h2_to_e4m3x2(h8.y) << 16);
            o.y = h2_to_e4m3x2(h8.z) | (h2_to_e4m3x2(h8.w) << 16);
            dst[idx] = o;
        }
        const uint4* asrc = (const uint4*)(g_K8 + (size_t)i0 * N);
        uint4* adst = (uint4*)s_pref;
#pragma unroll
        for (int s = 0; s < 4; ++s) {
            const int idx = s * NT + tid;
            adst[idx] = __ldcg(asrc + idx);
        }
    }
    __syncthreads();

    // ---------- fp8 iterations ----------
    for (int it = 0; it < NIT8; ++it) {
        // BF = bt^2 / (1 + K^T @ AF)  -- strip fully SMEM
        ((uint2*)s_vh)[tid] = __ldcg((const uint2*)g_AFh + tid);
        __syncthreads();
        {
            float acc[4] = {0.f, 0.f, 0.f, 0.f};
            const uint4* vh4 = (const uint4*)((const char*)s_vh + (q << 11));
            dot8_body(s_strip + (size_t)r0 * N + c0, false, vh4, lane, acc);
            warp_reduce_part(acc, r0, q, lane, s_part);
        }
        __syncthreads();
        if (tid < 32) {
            const float a = s_part[tid * 4] + s_part[tid * 4 + 1]
                          + s_part[tid * 4 + 2] + s_part[tid * 4 + 3];
            publish_seg(r_bt2 / (1.0f + a), i0, lane, g_BFf, g_BFh);
        }
        grid_sync_pub(tgt += NB);

        // AF = AT / (1 + K @ BF)  -- groups 0..3 SMEM half, 4..7 L2
        ((uint2*)s_vh)[tid] = __ldcg((const uint2*)g_BFh + tid);
        __syncthreads();
        {
            float acc[4] = {0.f, 0.f, 0.f, 0.f};
            const uint4* vh4 = (const uint4*)((const char*)s_vh + (q << 11));
            if (g < 4) dot8_body(s_pref + (size_t)r0 * N + c0, false, vh4, lane, acc);
            else       dot8_body(g_K8 + (size_t)(i0 + r0) * N + c0, true, vh4, lane, acc);
            warp_reduce_part(acc, r0, q, lane, s_part);
        }
        __syncthreads();
        if (tid < 32) {
            const float a = s_part[tid * 4] + s_part[tid * 4 + 1]
                          + s_part[tid * 4 + 2] + s_part[tid * 4 + 3];
            publish_seg(r_at / (1.0f + a), i0, lane, g_AFf, g_AFh);
        }
        grid_sync_pub(tgt += NB);
    }

    // ---------- fp16 refinement iterations (fp32-only publishes) ----------
    for (int it = 0; it < NIT16; ++it) {
        ((float4*)s_vec)[tid] = __ldcg((const float4*)g_AFf + tid);
        __syncthreads();
        dot16(g_KhT, s_vec, i0, g, q, lane, s_part);
        __syncthreads();
        if (tid < 32) {
            const float a = s_part[tid * 4] + s_part[tid * 4 + 1]
                          + s_part[tid * 4 + 2] + s_part[tid * 4 + 3];
            publish_seg_f(r_bt2 / (1.0f + a), i0, lane, g_BFf);
        }
        grid_sync_pub(tgt += NB);

        ((float4*)s_vec)[tid] = __ldcg((const float4*)g_BFf + tid);
        __syncthreads();
        dot16(g_Kh, s_vec, i0, g, q, lane, s_part);
        __syncthreads();
        if (tid < 32) {
            const float a = s_part[tid * 4] + s_part[tid * 4 + 1]
                          + s_part[tid * 4 + 2] + s_part[tid * 4 + 3];
            const float af = r_at / (1.0f + a);
            if (it == NIT16 - 1) s_af[tid] = af;           // final: keep local
            else                 publish_seg_f(af, i0, lane, g_AFf);
        }
        if (it != NIT16 - 1) grid_sync_pub(tgt += NB);
        else                 __syncthreads();              // BF already grid-synced
    }

    // ---------- output: C[i][j] = AF_i * k_ij^2 * BF_j  (fp32 k, streaming stores) ----------
    ((float4*)s_vec)[tid] = __ldcg((const float4*)g_BFf + tid);
    __syncthreads();

    const float af = s_af[w];                              // warp w -> row i0 + w
    const float4* sv4 = (const float4*)s_vec;
#pragma unroll 8
    for (int s = 0; s < 32; ++s) {
        const int j = s * 128 + lane * 4;
        const size_t off = (size_t)(i0 + w) * N + j;
        const float4 kv = __ldcs((const float4*)(k + off));
        const float4 bv = sv4[j >> 2];
        float4 c4;
        c4.x = af * kv.x * kv.x * bv.x;
        c4.y = af * kv.y * kv.y * bv.y;
        c4.z = af * kv.z * kv.z * bv.z;
        c4.w = af * kv.w * kv.w * bv.w;
        __stcs((float4*)(C + off), c4);
    }
}

extern "C" void kernel_launch(void* const* d_in, const int* in_sizes, int n_in,
                              void* d_out, int out_size) {
    const float* AT = (const float*)d_in[0];
    const float* k  = (const float*)d_in[1];
    const float* bt = (const float*)d_in[2];
    float* C = (float*)d_out;

    cudaFuncSetAttribute(competitive_kernel,
                         cudaFuncAttributeMaxDynamicSharedMemorySize, SMEM_DYN);
    reset_bar_kernel<<<1, 1>>>();
    competitive_kernel<<<NB, NT, SMEM_DYN>>>(AT, k, bt, C);
}